// round 5
// baseline (speedup 1.0000x reference)
#include <cuda_runtime.h>
#include <cuda_bf16.h>
#include <cstdint>

// ---------------- problem constants ----------------
#define NCELL 512
#define NDRUG 256
#define DCDIM 512
#define DDDIM 278
#define HDIM  512
#define FDIM  64
#define NPOS  (NCELL * NDRUG)          // 131072
#define OUT_FULL (NPOS + NPOS * FDIM)  // 8519680

// ---------------- device scratch ----------------
__device__ float g_cmat[NCELL * HDIM];              // cellpos @ W1[:512]
__device__ float g_dmat[NDRUG * HDIM];              // drugpos @ W1[512:]
// B fragments in exact mma register order:
// index ((ch*4+s)*4+p)*64 + lane*2  -> [hi uint4, lo uint4]
__device__ uint4 g_w2frag[8 * 4 * 4 * 32 * 2];      // 128 KB

// ---------------- helpers ----------------
__device__ __forceinline__ uint32_t smem_u32(const void* p) {
    uint32_t a;
    asm("{ .reg .u64 t; cvta.to.shared.u64 t, %1; cvt.u32.u64 %0, t; }"
        : "=r"(a) : "l"(p));
    return a;
}
#define LDM4(r, addr) \
    asm volatile("ldmatrix.sync.aligned.m8n8.x4.shared.b16 {%0,%1,%2,%3}, [%4];" \
                 : "=r"((r)[0]), "=r"((r)[1]), "=r"((r)[2]), "=r"((r)[3]) \
                 : "r"(addr))
#define MMA16816(d, a, b0v, b1v) \
    asm volatile("mma.sync.aligned.m16n8k16.row.col.f32.bf16.bf16.f32 " \
                 "{%0,%1,%2,%3}, {%4,%5,%6,%7}, {%8,%9}, {%0,%1,%2,%3};" \
                 : "+f"((d)[0]), "+f"((d)[1]), "+f"((d)[2]), "+f"((d)[3]) \
                 : "r"((a)[0]), "r"((a)[1]), "r"((a)[2]), "r"((a)[3]), \
                   "r"(b0v), "r"(b1v))

__device__ __forceinline__ uint32_t pack_bf16x2(float x0, float x1) {
    uint32_t r;
    asm("cvt.rn.bf16x2.f32 %0, %1, %2;" : "=r"(r) : "f"(x1), "f"(x0));
    return r;
}
__device__ __forceinline__ float bf_low_f(uint32_t h)  { return __uint_as_float(h << 16); }
__device__ __forceinline__ float bf_high_f(uint32_t h) { return __uint_as_float(h & 0xffff0000u); }

// ---------------- kernel 1: layer-1 GEMMs + W2 fragment precompute ----------------
#define L1_PITCH 68

__global__ void __launch_bounds__(256) layer1_v2(const float* __restrict__ cellpos,
                                                 const float* __restrict__ drugpos,
                                                 const float* __restrict__ W1,
                                                 const float* __restrict__ W2) {
    const int b = blockIdx.x;
    const int tid = threadIdx.x;

    if (b >= 96) {
        // ---- W2 -> split bf16 hi/lo -> ldmatrix fragments -> g_w2frag ----
        const int ch = b - 96;                       // k-chunk 0..7
        __shared__ __nv_bfloat16 hi[64][72];         // [n][k], 144B pitch
        __shared__ __nv_bfloat16 lo[64][72];
#pragma unroll
        for (int t = 0; t < 16; t++) {
            int idx = t * 256 + tid;                 // 0..4095
            int n = idx >> 6, kk = idx & 63;
            float wv = W2[(ch * 64 + kk) * 64 + n];  // W2 is [k][n]
            __nv_bfloat16 h = __float2bfloat16(wv);
            hi[n][kk] = h;
            lo[n][kk] = __float2bfloat16(wv - __bfloat162float(h));
        }
        __syncthreads();
        const int w8 = tid >> 5, lane = tid & 31;
        const int s = w8 >> 1;                       // k-step 0..3
        const int p0 = (w8 & 1) * 2;                 // n-group pair
        const uint32_t hbase = smem_u32(&hi[0][0]);
        const uint32_t lbase = smem_u32(&lo[0][0]);
        const uint32_t boff = (uint32_t)((((lane >> 4) * 8) + (lane & 7)) * 144 + ((lane >> 3) & 1) * 16);
#pragma unroll
        for (int q = 0; q < 2; q++) {
            const int p = p0 + q;
            uint32_t bh4[4], bl4[4];
            LDM4(bh4, hbase + boff + p * (16 * 144) + s * 32);
            LDM4(bl4, lbase + boff + p * (16 * 144) + s * 32);
            uint4* dst = g_w2frag + (((size_t)(ch * 4 + s) * 4 + p) * 64 + lane * 2);
            dst[0] = make_uint4(bh4[0], bh4[1], bh4[2], bh4[3]);
            dst[1] = make_uint4(bl4[0], bl4[1], bl4[2], bl4[3]);
        }
        return;
    }

    __shared__ __align__(16) float As[2][16][L1_PITCH];
    __shared__ __align__(16) float Bs[2][16][L1_PITCH];

    const float* X; const float* W; float* out; int K; bool cpath; int rt, ct;
    if (b < 64) { cpath = true;  rt = b >> 3;        ct = b & 7; X = cellpos; W = W1;             out = g_cmat; K = DCDIM; }
    else        { cpath = false; rt = (b - 64) >> 3; ct = b & 7; X = drugpos; W = W1 + 512 * 512; out = g_dmat; K = DDDIM; }
    const int row0 = rt * 64, col0 = ct * 64;

    const int am = tid >> 2;
    const int ak = (tid & 3) * 4;
    const int bk = tid >> 4;
    const int bn = (tid & 15) * 4;
    const int nch = (K + 15) >> 4;

    float4 ga, gb;
    if (cpath) {
        ga = *(const float4*)(X + (size_t)(row0 + am) * 512 + ak);
    } else {
        float v0 = (ak + 0 < K) ? X[(size_t)(row0 + am) * DDDIM + ak + 0] : 0.f;
        float v1 = (ak + 1 < K) ? X[(size_t)(row0 + am) * DDDIM + ak + 1] : 0.f;
        float v2 = (ak + 2 < K) ? X[(size_t)(row0 + am) * DDDIM + ak + 2] : 0.f;
        float v3 = (ak + 3 < K) ? X[(size_t)(row0 + am) * DDDIM + ak + 3] : 0.f;
        ga = make_float4(v0, v1, v2, v3);
    }
    gb = (bk < K) ? *(const float4*)(W + (size_t)bk * 512 + col0 + bn)
                  : make_float4(0.f, 0.f, 0.f, 0.f);
    As[0][ak + 0][am] = ga.x; As[0][ak + 1][am] = ga.y;
    As[0][ak + 2][am] = ga.z; As[0][ak + 3][am] = ga.w;
    *(float4*)&Bs[0][bk][bn] = gb;
    __syncthreads();

    const int tn = tid & 15, tm = tid >> 4;
    float acc[4][4] = {};

    for (int t = 0; t < nch; t++) {
        const int cur = t & 1;
        if (t + 1 < nch) {
            const int k0 = (t + 1) << 4;
            if (cpath) {
                ga = *(const float4*)(X + (size_t)(row0 + am) * 512 + k0 + ak);
            } else {
                float v0 = (k0 + ak + 0 < K) ? X[(size_t)(row0 + am) * DDDIM + k0 + ak + 0] : 0.f;
                float v1 = (k0 + ak + 1 < K) ? X[(size_t)(row0 + am) * DDDIM + k0 + ak + 1] : 0.f;
                float v2 = (k0 + ak + 2 < K) ? X[(size_t)(row0 + am) * DDDIM + k0 + ak + 2] : 0.f;
                float v3 = (k0 + ak + 3 < K) ? X[(size_t)(row0 + am) * DDDIM + k0 + ak + 3] : 0.f;
                ga = make_float4(v0, v1, v2, v3);
            }
            gb = (k0 + bk < K) ? *(const float4*)(W + (size_t)(k0 + bk) * 512 + col0 + bn)
                               : make_float4(0.f, 0.f, 0.f, 0.f);
        }
#pragma unroll
        for (int k = 0; k < 16; k++) {
            float4 a4 = *(const float4*)&As[cur][k][tm * 4];
            float4 b4 = *(const float4*)&Bs[cur][k][tn * 4];
            acc[0][0] = fmaf(a4.x, b4.x, acc[0][0]); acc[0][1] = fmaf(a4.x, b4.y, acc[0][1]);
            acc[0][2] = fmaf(a4.x, b4.z, acc[0][2]); acc[0][3] = fmaf(a4.x, b4.w, acc[0][3]);
            acc[1][0] = fmaf(a4.y, b4.x, acc[1][0]); acc[1][1] = fmaf(a4.y, b4.y, acc[1][1]);
            acc[1][2] = fmaf(a4.y, b4.z, acc[1][2]); acc[1][3] = fmaf(a4.y, b4.w, acc[1][3]);
            acc[2][0] = fmaf(a4.z, b4.x, acc[2][0]); acc[2][1] = fmaf(a4.z, b4.y, acc[2][1]);
            acc[2][2] = fmaf(a4.z, b4.z, acc[2][2]); acc[2][3] = fmaf(a4.z, b4.w, acc[2][3]);
            acc[3][0] = fmaf(a4.w, b4.x, acc[3][0]); acc[3][1] = fmaf(a4.w, b4.y, acc[3][1]);
            acc[3][2] = fmaf(a4.w, b4.z, acc[3][2]); acc[3][3] = fmaf(a4.w, b4.w, acc[3][3]);
        }
        if (t + 1 < nch) {
            const int nxt = cur ^ 1;
            As[nxt][ak + 0][am] = ga.x; As[nxt][ak + 1][am] = ga.y;
            As[nxt][ak + 2][am] = ga.z; As[nxt][ak + 3][am] = ga.w;
            *(float4*)&Bs[nxt][bk][bn] = gb;
        }
        __syncthreads();
    }

#pragma unroll
    for (int r = 0; r < 4; r++) {
        *(float4*)(out + (size_t)(row0 + tm * 4 + r) * 512 + col0 + tn * 4) =
            make_float4(acc[r][0], acc[r][1], acc[r][2], acc[r][3]);
    }
}

// ---------------- kernel 2: main fused kernel ----------------
// grid NCELL (1 cell/CTA), 128 threads (4 warps x 64 drug rows = 256 drugs).
// A fragments in regs; B fragments via pipelined LDG.128 from g_w2frag.
__global__ void __launch_bounds__(128, 2) graphcdr_main(const float* __restrict__ b1,
                                                        const float* __restrict__ b2,
                                                        const float* __restrict__ W3,
                                                        const float* __restrict__ b3,
                                                        float* __restrict__ out,
                                                        int out_size) {
    __shared__ float cb[HDIM];
    __shared__ float b2s[FDIM];
    __shared__ float w3s[FDIM];

    const int tid  = threadIdx.x;
    const int lane = tid & 31;
    const int w    = tid >> 5;                 // warp 0..3
    const int i    = blockIdx.x;               // cell

#pragma unroll
    for (int q = 0; q < 4; q++) cb[q * 128 + tid] = g_cmat[i * HDIM + q * 128 + tid] + b1[q * 128 + tid];
    if (tid < FDIM) { b2s[tid] = b2[tid]; w3s[tid] = W3[tid]; }
    __syncthreads();

    // per-thread d pointer: row = w*64 + (lane>>2), col = 2*(lane&3)
    const float* dp0 = g_dmat + (size_t)(w * 64 + (lane >> 2)) * HDIM + 2 * (lane & 3);

    float acc[32][4];
#pragma unroll
    for (int q = 0; q < 32; q++) {
        acc[q][0] = 0.f; acc[q][1] = 0.f; acc[q][2] = 0.f; acc[q][3] = 0.f;
    }

    // d values: dv[mt][4]: (R,k),(R+8,k),(R,k+8),(R+8,k+8) as float2, mt row offset 16
    float2 dv[4][4];
#pragma unroll
    for (int mt = 0; mt < 4; mt++) {
        const float* p = dp0 + mt * (16 * HDIM);
        dv[mt][0] = *(const float2*)(p);
        dv[mt][1] = *(const float2*)(p + 8 * HDIM);
        dv[mt][2] = *(const float2*)(p + 8);
        dv[mt][3] = *(const float2*)(p + 8 * HDIM + 8);
    }

    const int laneK = 2 * (lane & 3);
    const uint4* fbase = g_w2frag + lane * 2;

    // fb pipeline: prefetch (ch=0,s=0,p=0)
    uint4 bhN = fbase[0];
    uint4 blN = fbase[1];

    for (int ch = 0; ch < 8; ch++) {
#pragma unroll
        for (int s = 0; s < 4; s++) {
            const int kk = ch * 64 + s * 16 + laneK;
            const float2 cb0 = *(const float2*)&cb[kk];
            const float2 cb1 = *(const float2*)&cb[kk + 8];

            uint32_t ah[4][4], al[4][4];
#pragma unroll
            for (int mt = 0; mt < 4; mt++) {
                float x0 = fmaxf(cb0.x + dv[mt][0].x, 0.f);
                float x1 = fmaxf(cb0.y + dv[mt][0].y, 0.f);
                float y0 = fmaxf(cb0.x + dv[mt][1].x, 0.f);
                float y1 = fmaxf(cb0.y + dv[mt][1].y, 0.f);
                float x2 = fmaxf(cb1.x + dv[mt][2].x, 0.f);
                float x3 = fmaxf(cb1.y + dv[mt][2].y, 0.f);
                float y2 = fmaxf(cb1.x + dv[mt][3].x, 0.f);
                float y3 = fmaxf(cb1.y + dv[mt][3].y, 0.f);
                uint32_t h0 = pack_bf16x2(x0, x1);
                uint32_t h1 = pack_bf16x2(y0, y1);
                uint32_t h2 = pack_bf16x2(x2, x3);
                uint32_t h3 = pack_bf16x2(y2, y3);
                ah[mt][0] = h0; ah[mt][1] = h1; ah[mt][2] = h2; ah[mt][3] = h3;
                al[mt][0] = pack_bf16x2(x0 - bf_low_f(h0), x1 - bf_high_f(h0));
                al[mt][1] = pack_bf16x2(y0 - bf_low_f(h1), y1 - bf_high_f(h1));
                al[mt][2] = pack_bf16x2(x2 - bf_low_f(h2), x3 - bf_high_f(h2));
                al[mt][3] = pack_bf16x2(y2 - bf_low_f(h3), y3 - bf_high_f(h3));
            }

            // prefetch d for next s
            if (ch * 4 + s < 31) {
                const int kn = ch * 64 + (s + 1) * 16;
#pragma unroll
                for (int mt = 0; mt < 4; mt++) {
                    const float* p = dp0 + mt * (16 * HDIM) + kn;
                    dv[mt][0] = *(const float2*)(p);
                    dv[mt][1] = *(const float2*)(p + 8 * HDIM);
                    dv[mt][2] = *(const float2*)(p + 8);
                    dv[mt][3] = *(const float2*)(p + 8 * HDIM + 8);
                }
            }

            const size_t sbase = (size_t)(ch * 4 + s) * 256;   // uint4 units
#pragma unroll
            for (int p = 0; p < 4; p++) {
                const uint4 bh = bhN;
                const uint4 bl = blN;
                // prefetch next (p+1), or next s's p=0
                if (p < 3) {
                    bhN = fbase[sbase + (p + 1) * 64];
                    blN = fbase[sbase + (p + 1) * 64 + 1];
                } else if (ch * 4 + s < 31) {
                    bhN = fbase[sbase + 256];
                    blN = fbase[sbase + 256 + 1];
                }
#pragma unroll
                for (int mt = 0; mt < 4; mt++) {
                    float* a0 = acc[mt * 8 + p * 2];
                    float* a1 = acc[mt * 8 + p * 2 + 1];
                    MMA16816(a0, ah[mt], bh.x, bh.y);
                    MMA16816(a1, ah[mt], bh.z, bh.w);
                    MMA16816(a0, ah[mt], bl.x, bl.y);
                    MMA16816(a1, ah[mt], bl.z, bl.w);
                    MMA16816(a0, al[mt], bh.x, bh.y);
                    MMA16816(a1, al[mt], bh.z, bh.w);
                }
            }
        }
    }

    // ---- epilogue ----
    const float b3v = b3[0];
    const int r  = lane >> 2;
    const int cq = 2 * (lane & 3);
    const bool wf = (out_size >= OUT_FULL);
    float* featbase = out + NPOS + ((size_t)i * NDRUG) * FDIM;
#pragma unroll
    for (int mt = 0; mt < 4; mt++) {
        const int row0 = w * 64 + mt * 16 + r;   // drug row
        const int row1 = row0 + 8;
        float s0 = 0.f, s1 = 0.f;
#pragma unroll
        for (int nt = 0; nt < 8; nt++) {
            const int c = nt * 8 + cq;
            float v00 = fmaxf(acc[mt * 8 + nt][0] + b2s[c],     0.f);
            float v01 = fmaxf(acc[mt * 8 + nt][1] + b2s[c + 1], 0.f);
            float v10 = fmaxf(acc[mt * 8 + nt][2] + b2s[c],     0.f);
            float v11 = fmaxf(acc[mt * 8 + nt][3] + b2s[c + 1], 0.f);
            s0 = fmaf(v00, w3s[c], fmaf(v01, w3s[c + 1], s0));
            s1 = fmaf(v10, w3s[c], fmaf(v11, w3s[c + 1], s1));
            if (wf) {
                *(float2*)(featbase + (size_t)row0 * FDIM + c) = make_float2(v00, v01);
                *(float2*)(featbase + (size_t)row1 * FDIM + c) = make_float2(v10, v11);
            }
        }
        s0 += __shfl_xor_sync(0xffffffffu, s0, 1);
        s0 += __shfl_xor_sync(0xffffffffu, s0, 2);
        s1 += __shfl_xor_sync(0xffffffffu, s1, 1);
        s1 += __shfl_xor_sync(0xffffffffu, s1, 2);
        if ((lane & 3) == 0) {
            out[(size_t)i * NDRUG + row0] = 1.f / (1.f + expf(-(b3v + s0)));
            out[(size_t)i * NDRUG + row1] = 1.f / (1.f + expf(-(b3v + s1)));
        }
    }
}

// ---------------- launch ----------------
extern "C" void kernel_launch(void* const* d_in, const int* in_sizes, int n_in,
                              void* d_out, int out_size) {
    if (n_in < 8) return;
    const float* cellpos = (const float*)d_in[0];
    const float* drugpos = (const float*)d_in[1];
    const float* W1      = (const float*)d_in[2];
    const float* b1      = (const float*)d_in[3];
    const float* W2      = (const float*)d_in[4];
    const float* b2      = (const float*)d_in[5];
    const float* W3      = (const float*)d_in[6];
    const float* b3      = (const float*)d_in[7];
    float* out = (float*)d_out;

    layer1_v2<<<104, 256>>>(cellpos, drugpos, W1, W2);
    graphcdr_main<<<NCELL, 128>>>(b1, b2, W3, b3, out, out_size);
}

// round 15
// speedup vs baseline: 1.0535x; 1.0535x over previous
#include <cuda_runtime.h>
#include <cuda_bf16.h>
#include <cstdint>

// ---------------- problem constants ----------------
#define NCELL 512
#define NDRUG 256
#define DCDIM 512
#define DDDIM 278
#define HDIM  512
#define FDIM  64
#define NPOS  (NCELL * NDRUG)          // 131072
#define OUT_FULL (NPOS + NPOS * FDIM)  // 8519680

// ---------------- device scratch ----------------
__device__ float g_cmat[NCELL * HDIM];              // cellpos @ W1[:512]
__device__ float g_dmat[NDRUG * HDIM];              // drugpos @ W1[512:]
// B fragments in exact mma register order:
// index ((ch*4+s)*4+p)*64 + lane*2  -> [hi uint4, lo uint4]
__device__ uint4 g_w2frag[8 * 4 * 4 * 32 * 2];      // 128 KB

// ---------------- helpers ----------------
__device__ __forceinline__ uint32_t smem_u32(const void* p) {
    uint32_t a;
    asm("{ .reg .u64 t; cvta.to.shared.u64 t, %1; cvt.u32.u64 %0, t; }"
        : "=r"(a) : "l"(p));
    return a;
}
#define LDM4(r, addr) \
    asm volatile("ldmatrix.sync.aligned.m8n8.x4.shared.b16 {%0,%1,%2,%3}, [%4];" \
                 : "=r"((r)[0]), "=r"((r)[1]), "=r"((r)[2]), "=r"((r)[3]) \
                 : "r"(addr))
#define MMA16816(d, a, b0v, b1v) \
    asm volatile("mma.sync.aligned.m16n8k16.row.col.f32.bf16.bf16.f32 " \
                 "{%0,%1,%2,%3}, {%4,%5,%6,%7}, {%8,%9}, {%0,%1,%2,%3};" \
                 : "+f"((d)[0]), "+f"((d)[1]), "+f"((d)[2]), "+f"((d)[3]) \
                 : "r"((a)[0]), "r"((a)[1]), "r"((a)[2]), "r"((a)[3]), \
                   "r"(b0v), "r"(b1v))

__device__ __forceinline__ uint32_t pack_bf16x2(float x0, float x1) {
    uint32_t r;
    asm("cvt.rn.bf16x2.f32 %0, %1, %2;" : "=r"(r) : "f"(x1), "f"(x0));
    return r;
}
__device__ __forceinline__ float bf_low_f(uint32_t h)  { return __uint_as_float(h << 16); }
__device__ __forceinline__ float bf_high_f(uint32_t h) { return __uint_as_float(h & 0xffff0000u); }

// ---------------- kernel 1: layer-1 GEMMs + W2 fragment precompute ----------------
#define L1_PITCH 68

__global__ void __launch_bounds__(256) layer1_v2(const float* __restrict__ cellpos,
                                                 const float* __restrict__ drugpos,
                                                 const float* __restrict__ W1,
                                                 const float* __restrict__ W2) {
    const int b = blockIdx.x;
    const int tid = threadIdx.x;

    if (b >= 96) {
        // ---- W2 -> split bf16 hi/lo -> ldmatrix fragments -> g_w2frag ----
        const int ch = b - 96;                       // k-chunk 0..7
        __shared__ __nv_bfloat16 hi[64][72];         // [n][k], 144B pitch
        __shared__ __nv_bfloat16 lo[64][72];
#pragma unroll
        for (int t = 0; t < 16; t++) {
            int idx = t * 256 + tid;                 // 0..4095
            int n = idx >> 6, kk = idx & 63;
            float wv = W2[(ch * 64 + kk) * 64 + n];  // W2 is [k][n]
            __nv_bfloat16 h = __float2bfloat16(wv);
            hi[n][kk] = h;
            lo[n][kk] = __float2bfloat16(wv - __bfloat162float(h));
        }
        __syncthreads();
        const int w8 = tid >> 5, lane = tid & 31;
        const int s = w8 >> 1;                       // k-step 0..3
        const int p0 = (w8 & 1) * 2;                 // n-group pair
        const uint32_t hbase = smem_u32(&hi[0][0]);
        const uint32_t lbase = smem_u32(&lo[0][0]);
        const uint32_t boff = (uint32_t)((((lane >> 4) * 8) + (lane & 7)) * 144 + ((lane >> 3) & 1) * 16);
#pragma unroll
        for (int q = 0; q < 2; q++) {
            const int p = p0 + q;
            uint32_t bh4[4], bl4[4];
            LDM4(bh4, hbase + boff + p * (16 * 144) + s * 32);
            LDM4(bl4, lbase + boff + p * (16 * 144) + s * 32);
            uint4* dst = g_w2frag + (((size_t)(ch * 4 + s) * 4 + p) * 64 + lane * 2);
            dst[0] = make_uint4(bh4[0], bh4[1], bh4[2], bh4[3]);
            dst[1] = make_uint4(bl4[0], bl4[1], bl4[2], bl4[3]);
        }
        return;
    }

    __shared__ __align__(16) float As[2][16][L1_PITCH];
    __shared__ __align__(16) float Bs[2][16][L1_PITCH];

    const float* X; const float* W; float* out; int K; bool cpath; int rt, ct;
    if (b < 64) { cpath = true;  rt = b >> 3;        ct = b & 7; X = cellpos; W = W1;             out = g_cmat; K = DCDIM; }
    else        { cpath = false; rt = (b - 64) >> 3; ct = b & 7; X = drugpos; W = W1 + 512 * 512; out = g_dmat; K = DDDIM; }
    const int row0 = rt * 64, col0 = ct * 64;

    const int am = tid >> 2;
    const int ak = (tid & 3) * 4;
    const int bk = tid >> 4;
    const int bn = (tid & 15) * 4;
    const int nch = (K + 15) >> 4;

    float4 ga, gb;
    if (cpath) {
        ga = *(const float4*)(X + (size_t)(row0 + am) * 512 + ak);
    } else {
        float v0 = (ak + 0 < K) ? X[(size_t)(row0 + am) * DDDIM + ak + 0] : 0.f;
        float v1 = (ak + 1 < K) ? X[(size_t)(row0 + am) * DDDIM + ak + 1] : 0.f;
        float v2 = (ak + 2 < K) ? X[(size_t)(row0 + am) * DDDIM + ak + 2] : 0.f;
        float v3 = (ak + 3 < K) ? X[(size_t)(row0 + am) * DDDIM + ak + 3] : 0.f;
        ga = make_float4(v0, v1, v2, v3);
    }
    gb = (bk < K) ? *(const float4*)(W + (size_t)bk * 512 + col0 + bn)
                  : make_float4(0.f, 0.f, 0.f, 0.f);
    As[0][ak + 0][am] = ga.x; As[0][ak + 1][am] = ga.y;
    As[0][ak + 2][am] = ga.z; As[0][ak + 3][am] = ga.w;
    *(float4*)&Bs[0][bk][bn] = gb;
    __syncthreads();

    const int tn = tid & 15, tm = tid >> 4;
    float acc[4][4] = {};

    for (int t = 0; t < nch; t++) {
        const int cur = t & 1;
        if (t + 1 < nch) {
            const int k0 = (t + 1) << 4;
            if (cpath) {
                ga = *(const float4*)(X + (size_t)(row0 + am) * 512 + k0 + ak);
            } else {
                float v0 = (k0 + ak + 0 < K) ? X[(size_t)(row0 + am) * DDDIM + k0 + ak + 0] : 0.f;
                float v1 = (k0 + ak + 1 < K) ? X[(size_t)(row0 + am) * DDDIM + k0 + ak + 1] : 0.f;
                float v2 = (k0 + ak + 2 < K) ? X[(size_t)(row0 + am) * DDDIM + k0 + ak + 2] : 0.f;
                float v3 = (k0 + ak + 3 < K) ? X[(size_t)(row0 + am) * DDDIM + k0 + ak + 3] : 0.f;
                ga = make_float4(v0, v1, v2, v3);
            }
            gb = (k0 + bk < K) ? *(const float4*)(W + (size_t)(k0 + bk) * 512 + col0 + bn)
                               : make_float4(0.f, 0.f, 0.f, 0.f);
        }
#pragma unroll
        for (int k = 0; k < 16; k++) {
            float4 a4 = *(const float4*)&As[cur][k][tm * 4];
            float4 b4 = *(const float4*)&Bs[cur][k][tn * 4];
            acc[0][0] = fmaf(a4.x, b4.x, acc[0][0]); acc[0][1] = fmaf(a4.x, b4.y, acc[0][1]);
            acc[0][2] = fmaf(a4.x, b4.z, acc[0][2]); acc[0][3] = fmaf(a4.x, b4.w, acc[0][3]);
            acc[1][0] = fmaf(a4.y, b4.x, acc[1][0]); acc[1][1] = fmaf(a4.y, b4.y, acc[1][1]);
            acc[1][2] = fmaf(a4.y, b4.z, acc[1][2]); acc[1][3] = fmaf(a4.y, b4.w, acc[1][3]);
            acc[2][0] = fmaf(a4.z, b4.x, acc[2][0]); acc[2][1] = fmaf(a4.z, b4.y, acc[2][1]);
            acc[2][2] = fmaf(a4.z, b4.z, acc[2][2]); acc[2][3] = fmaf(a4.z, b4.w, acc[2][3]);
            acc[3][0] = fmaf(a4.w, b4.x, acc[3][0]); acc[3][1] = fmaf(a4.w, b4.y, acc[3][1]);
            acc[3][2] = fmaf(a4.w, b4.z, acc[3][2]); acc[3][3] = fmaf(a4.w, b4.w, acc[3][3]);
        }
        if (t + 1 < nch) {
            const int nxt = cur ^ 1;
            As[nxt][ak + 0][am] = ga.x; As[nxt][ak + 1][am] = ga.y;
            As[nxt][ak + 2][am] = ga.z; As[nxt][ak + 3][am] = ga.w;
            *(float4*)&Bs[nxt][bk][bn] = gb;
        }
        __syncthreads();
    }

#pragma unroll
    for (int r = 0; r < 4; r++) {
        *(float4*)(out + (size_t)(row0 + tm * 4 + r) * 512 + col0 + tn * 4) =
            make_float4(acc[r][0], acc[r][1], acc[r][2], acc[r][3]);
    }
}

// ---------------- kernel 2: main fused kernel ----------------
// grid (NCELL, 2), 128 threads, warp tile 32x64 (mt=2).
// A fragments in regs; all 4 p-groups' B fragments loaded up front;
// MMAs issued pass-major so same-acc reuse distance = 14 MMAs.
__global__ void __launch_bounds__(128, 3) graphcdr_main(const float* __restrict__ b1,
                                                        const float* __restrict__ b2,
                                                        const float* __restrict__ W3,
                                                        const float* __restrict__ b3,
                                                        float* __restrict__ out,
                                                        int out_size) {
    __shared__ float cb[HDIM];
    __shared__ float b2s[FDIM];
    __shared__ float w3s[FDIM];

    const int tid  = threadIdx.x;
    const int lane = tid & 31;
    const int w    = tid >> 5;                 // warp 0..3
    const int i    = blockIdx.x;               // cell
    const int jbase = blockIdx.y * 128;        // drug row base

#pragma unroll
    for (int q = 0; q < 4; q++) cb[q * 128 + tid] = g_cmat[i * HDIM + q * 128 + tid] + b1[q * 128 + tid];
    if (tid < FDIM) { b2s[tid] = b2[tid]; w3s[tid] = W3[tid]; }
    const float b3v = b3[0];
    __syncthreads();

    // per-thread d pointer: row = jbase + w*32 + (lane>>2), col = 2*(lane&3)
    const float* dp0 = g_dmat + (size_t)(jbase + w * 32 + (lane >> 2)) * HDIM + 2 * (lane & 3);

    float acc[16][4];
#pragma unroll
    for (int q = 0; q < 16; q++) {
        acc[q][0] = 0.f; acc[q][1] = 0.f; acc[q][2] = 0.f; acc[q][3] = 0.f;
    }

    // d values: (R,k),(R+8,k),(R,k+8),(R+8,k+8) as float2
    float2 dv[2][4];
#pragma unroll
    for (int mt = 0; mt < 2; mt++) {
        const float* p = dp0 + mt * (16 * HDIM);
        dv[mt][0] = *(const float2*)(p);
        dv[mt][1] = *(const float2*)(p + 8 * HDIM);
        dv[mt][2] = *(const float2*)(p + 8);
        dv[mt][3] = *(const float2*)(p + 8 * HDIM + 8);
    }

    const int laneK = 2 * (lane & 3);
    const uint4* fbase = g_w2frag + lane * 2;

    for (int ch = 0; ch < 8; ch++) {
#pragma unroll
        for (int s = 0; s < 4; s++) {
            // ---- issue all fb loads first (L1 hits after first warp) ----
            const size_t sbase = (size_t)(ch * 4 + s) * 256;   // uint4 units
            uint4 bh[4], bl[4];
#pragma unroll
            for (int p = 0; p < 4; p++) {
                bh[p] = fbase[sbase + p * 64];
                bl[p] = fbase[sbase + p * 64 + 1];
            }

            // ---- build A fragments while fb loads are in flight ----
            const int kk = ch * 64 + s * 16 + laneK;
            const float2 cb0 = *(const float2*)&cb[kk];
            const float2 cb1 = *(const float2*)&cb[kk + 8];

            uint32_t ah[2][4], al[2][4];
#pragma unroll
            for (int mt = 0; mt < 2; mt++) {
                float x0 = fmaxf(cb0.x + dv[mt][0].x, 0.f);
                float x1 = fmaxf(cb0.y + dv[mt][0].y, 0.f);
                float y0 = fmaxf(cb0.x + dv[mt][1].x, 0.f);
                float y1 = fmaxf(cb0.y + dv[mt][1].y, 0.f);
                float x2 = fmaxf(cb1.x + dv[mt][2].x, 0.f);
                float x3 = fmaxf(cb1.y + dv[mt][2].y, 0.f);
                float y2 = fmaxf(cb1.x + dv[mt][3].x, 0.f);
                float y3 = fmaxf(cb1.y + dv[mt][3].y, 0.f);
                uint32_t h0 = pack_bf16x2(x0, x1);
                uint32_t h1 = pack_bf16x2(y0, y1);
                uint32_t h2 = pack_bf16x2(x2, x3);
                uint32_t h3 = pack_bf16x2(y2, y3);
                ah[mt][0] = h0; ah[mt][1] = h1; ah[mt][2] = h2; ah[mt][3] = h3;
                al[mt][0] = pack_bf16x2(x0 - bf_low_f(h0), x1 - bf_high_f(h0));
                al[mt][1] = pack_bf16x2(y0 - bf_low_f(h1), y1 - bf_high_f(h1));
                al[mt][2] = pack_bf16x2(x2 - bf_low_f(h2), x3 - bf_high_f(h2));
                al[mt][3] = pack_bf16x2(y2 - bf_low_f(h3), y3 - bf_high_f(h3));
            }

            // ---- prefetch d for next s ----
            if (ch * 4 + s < 31) {
                const int kn = ch * 64 + (s + 1) * 16;
#pragma unroll
                for (int mt = 0; mt < 2; mt++) {
                    const float* p = dp0 + mt * (16 * HDIM) + kn;
                    dv[mt][0] = *(const float2*)(p);
                    dv[mt][1] = *(const float2*)(p + 8 * HDIM);
                    dv[mt][2] = *(const float2*)(p + 8);
                    dv[mt][3] = *(const float2*)(p + 8 * HDIM + 8);
                }
            }

            // ---- 48 MMAs, pass-major: same-acc reuse distance = 14 ----
#pragma unroll
            for (int pass = 0; pass < 3; pass++) {
#pragma unroll
                for (int p = 0; p < 4; p++) {
                    const uint4 bb = (pass == 1) ? bl[p] : bh[p];
#pragma unroll
                    for (int mt = 0; mt < 2; mt++) {
                        const uint32_t* A = (pass == 2) ? al[mt] : ah[mt];
                        MMA16816(acc[mt * 8 + p * 2],     A, bb.x, bb.y);
                        MMA16816(acc[mt * 8 + p * 2 + 1], A, bb.z, bb.w);
                    }
                }
            }
        }
    }

    // ---- epilogue ----
    const int r  = lane >> 2;
    const int cq = 2 * (lane & 3);
    const bool wf = (out_size >= OUT_FULL);
    float* featbase = out + NPOS + ((size_t)i * NDRUG) * FDIM;
#pragma unroll
    for (int mt = 0; mt < 2; mt++) {
        const int row0 = jbase + w * 32 + mt * 16 + r;   // drug row
        const int row1 = row0 + 8;
        float s0 = 0.f, s1 = 0.f;
#pragma unroll
        for (int nt = 0; nt < 8; nt++) {
            const int c = nt * 8 + cq;
            float v00 = fmaxf(acc[mt * 8 + nt][0] + b2s[c],     0.f);
            float v01 = fmaxf(acc[mt * 8 + nt][1] + b2s[c + 1], 0.f);
            float v10 = fmaxf(acc[mt * 8 + nt][2] + b2s[c],     0.f);
            float v11 = fmaxf(acc[mt * 8 + nt][3] + b2s[c + 1], 0.f);
            s0 = fmaf(v00, w3s[c], fmaf(v01, w3s[c + 1], s0));
            s1 = fmaf(v10, w3s[c], fmaf(v11, w3s[c + 1], s1));
            if (wf) {
                *(float2*)(featbase + (size_t)row0 * FDIM + c) = make_float2(v00, v01);
                *(float2*)(featbase + (size_t)row1 * FDIM + c) = make_float2(v10, v11);
            }
        }
        s0 += __shfl_xor_sync(0xffffffffu, s0, 1);
        s0 += __shfl_xor_sync(0xffffffffu, s0, 2);
        s1 += __shfl_xor_sync(0xffffffffu, s1, 1);
        s1 += __shfl_xor_sync(0xffffffffu, s1, 2);
        if ((lane & 3) == 0) {
            out[(size_t)i * NDRUG + row0] = 1.f / (1.f + expf(-(b3v + s0)));
            out[(size_t)i * NDRUG + row1] = 1.f / (1.f + expf(-(b3v + s1)));
        }
    }
}

// ---------------- launch ----------------
extern "C" void kernel_launch(void* const* d_in, const int* in_sizes, int n_in,
                              void* d_out, int out_size) {
    if (n_in < 8) return;
    const float* cellpos = (const float*)d_in[0];
    const float* drugpos = (const float*)d_in[1];
    const float* W1      = (const float*)d_in[2];
    const float* b1      = (const float*)d_in[3];
    const float* W2      = (const float*)d_in[4];
    const float* b2      = (const float*)d_in[5];
    const float* W3      = (const float*)d_in[6];
    const float* b3      = (const float*)d_in[7];
    float* out = (float*)d_out;

    layer1_v2<<<104, 256>>>(cellpos, drugpos, W1, W2);
    graphcdr_main<<<dim3(NCELL, 2), 128>>>(b1, b2, W3, b3, out, out_size);
}